// round 16
// baseline (speedup 1.0000x reference)
#include <cuda_runtime.h>
#include <math.h>

#define NNODE 16384
#define MEDGE 4096
#define DIMSZ 1024

// Scratch (allocation-free rule: __device__ globals)
__device__ float g_hn[(size_t)NNODE * DIMSZ];   // 64 MB
__device__ float g_he[(size_t)MEDGE * DIMSZ];   // 16 MB

typedef unsigned long long u64;

__device__ __forceinline__ float lo32(u64 v) { return __uint_as_float((unsigned)(v & 0xffffffffu)); }
__device__ __forceinline__ float hi32(u64 v) { return __uint_as_float((unsigned)(v >> 32)); }

// C[M,Nc] = A[M,K] @ op(B), row-major everything.
// TRANSB=true : B is [Nc,K] (NT gemm, C = A @ B^T)
// TRANSB=false: B is [K,Nc] (NN gemm)
// EPI: 0 = plain, 1 = *scale then mask(H<=0 -> -1e9), 2 = elu
template <bool TRANSB, int EPI>
__global__ __launch_bounds__(256, 2)
void gemm128(const float* __restrict__ A, const float* __restrict__ Bm,
             float* __restrict__ C, int Nc, int K,
             const int* __restrict__ Hm, float scale)
{
    __shared__ __align__(16) float As[16][128];
    __shared__ __align__(16) float Bs[16][128];

    const int tid = threadIdx.x;
    const int tx  = tid & 15;       // n-subtile
    const int ty  = tid >> 4;       // m-subtile
    const int m0  = blockIdx.y << 7;
    const int n0  = blockIdx.x << 7;

    // A tile loader: row = tid&127, two quads at float offsets {q*4, q*4+8}
    const int arow = tid & 127;
    const int aq4  = (tid >> 7) << 2;   // 0 or 4
    const float* Ap = A + (size_t)(m0 + arow) * K + aq4;

    const float* Bp;
    int bk = 0, bq4 = 0;
    if (TRANSB) {
        Bp = Bm + (size_t)(n0 + arow) * K + aq4;
    } else {
        bk  = tid >> 5;              // 0..7 (and +8 for second load)
        bq4 = (tid & 31) << 2;       // 0..124
        Bp  = Bm + (size_t)bk * Nc + n0 + bq4;
    }

    // prologue: fetch tile 0
    float4 pa0 = *(const float4*)Ap;
    float4 pa1 = *(const float4*)(Ap + 8);
    float4 pb0, pb1;
    if (TRANSB) {
        pb0 = *(const float4*)Bp;
        pb1 = *(const float4*)(Bp + 8);
    } else {
        pb0 = *(const float4*)Bp;
        pb1 = *(const float4*)(Bp + (size_t)8 * Nc);
    }

    u64 acc[4][8];
#pragma unroll
    for (int i = 0; i < 4; i++)
#pragma unroll
        for (int j = 0; j < 8; j++) acc[i][j] = 0ull;

    const int ktiles = K >> 4;

    // store tile 0 to smem
    {
        As[aq4 + 0][arow] = pa0.x; As[aq4 + 1][arow] = pa0.y;
        As[aq4 + 2][arow] = pa0.z; As[aq4 + 3][arow] = pa0.w;
        As[aq4 + 8][arow] = pa1.x; As[aq4 + 9][arow] = pa1.y;
        As[aq4 +10][arow] = pa1.z; As[aq4 +11][arow] = pa1.w;
        if (TRANSB) {
            Bs[aq4 + 0][arow] = pb0.x; Bs[aq4 + 1][arow] = pb0.y;
            Bs[aq4 + 2][arow] = pb0.z; Bs[aq4 + 3][arow] = pb0.w;
            Bs[aq4 + 8][arow] = pb1.x; Bs[aq4 + 9][arow] = pb1.y;
            Bs[aq4 +10][arow] = pb1.z; Bs[aq4 +11][arow] = pb1.w;
        } else {
            *(float4*)&Bs[bk][bq4]     = pb0;
            *(float4*)&Bs[bk + 8][bq4] = pb1;
        }
    }
    __syncthreads();

    for (int kt = 0; kt < ktiles; ++kt) {
        // prefetch next tile into registers while computing current
        if (kt + 1 < ktiles) {
            Ap += 16;
            pa0 = *(const float4*)Ap;
            pa1 = *(const float4*)(Ap + 8);
            if (TRANSB) {
                Bp += 16;
                pb0 = *(const float4*)Bp;
                pb1 = *(const float4*)(Bp + 8);
            } else {
                Bp += (size_t)16 * Nc;
                pb0 = *(const float4*)Bp;
                pb1 = *(const float4*)(Bp + (size_t)8 * Nc);
            }
        }

#pragma unroll
        for (int k = 0; k < 16; ++k) {
            // 8 consecutive m-values as 4 packed f32x2 operands
            ulonglong2 a01 = *(const ulonglong2*)&As[k][ty << 3];
            ulonglong2 a23 = *(const ulonglong2*)&As[k][(ty << 3) + 4];
            float4 b0 = *(const float4*)&Bs[k][tx << 3];
            float4 b1 = *(const float4*)&Bs[k][(tx << 3) + 4];
            float bf[8] = {b0.x, b0.y, b0.z, b0.w, b1.x, b1.y, b1.z, b1.w};
#pragma unroll
            for (int j = 0; j < 8; ++j) {
                u64 bb;
                asm("mov.b64 %0, {%1, %1};" : "=l"(bb) : "r"(__float_as_uint(bf[j])));
                asm("fma.rn.f32x2 %0, %1, %2, %0;" : "+l"(acc[0][j]) : "l"(a01.x), "l"(bb));
                asm("fma.rn.f32x2 %0, %1, %2, %0;" : "+l"(acc[1][j]) : "l"(a01.y), "l"(bb));
                asm("fma.rn.f32x2 %0, %1, %2, %0;" : "+l"(acc[2][j]) : "l"(a23.x), "l"(bb));
                asm("fma.rn.f32x2 %0, %1, %2, %0;" : "+l"(acc[3][j]) : "l"(a23.y), "l"(bb));
            }
        }
        __syncthreads();

        if (kt + 1 < ktiles) {
            As[aq4 + 0][arow] = pa0.x; As[aq4 + 1][arow] = pa0.y;
            As[aq4 + 2][arow] = pa0.z; As[aq4 + 3][arow] = pa0.w;
            As[aq4 + 8][arow] = pa1.x; As[aq4 + 9][arow] = pa1.y;
            As[aq4 +10][arow] = pa1.z; As[aq4 +11][arow] = pa1.w;
            if (TRANSB) {
                Bs[aq4 + 0][arow] = pb0.x; Bs[aq4 + 1][arow] = pb0.y;
                Bs[aq4 + 2][arow] = pb0.z; Bs[aq4 + 3][arow] = pb0.w;
                Bs[aq4 + 8][arow] = pb1.x; Bs[aq4 + 9][arow] = pb1.y;
                Bs[aq4 +10][arow] = pb1.z; Bs[aq4 +11][arow] = pb1.w;
            } else {
                *(float4*)&Bs[bk][bq4]     = pb0;
                *(float4*)&Bs[bk + 8][bq4] = pb1;
            }
            __syncthreads();
        }
    }

    // Epilogue: acc[mp][j] holds C[m0+ty*8+2*mp+{lo,hi}][n0+tx*8+j]
#pragma unroll
    for (int mp = 0; mp < 4; ++mp) {
#pragma unroll
        for (int h = 0; h < 2; ++h) {
            const int r = m0 + (ty << 3) + (mp << 1) + h;
            float v[8];
#pragma unroll
            for (int j = 0; j < 8; ++j)
                v[j] = h ? hi32(acc[mp][j]) : lo32(acc[mp][j]);
            const size_t base = (size_t)r * Nc + n0 + (tx << 3);

            if (EPI == 1) {
                int4 h0 = *(const int4*)(Hm + base);
                int4 h1 = *(const int4*)(Hm + base + 4);
                v[0] = (h0.x > 0) ? v[0] * scale : -1e9f;
                v[1] = (h0.y > 0) ? v[1] * scale : -1e9f;
                v[2] = (h0.z > 0) ? v[2] * scale : -1e9f;
                v[3] = (h0.w > 0) ? v[3] * scale : -1e9f;
                v[4] = (h1.x > 0) ? v[4] * scale : -1e9f;
                v[5] = (h1.y > 0) ? v[5] * scale : -1e9f;
                v[6] = (h1.z > 0) ? v[6] * scale : -1e9f;
                v[7] = (h1.w > 0) ? v[7] * scale : -1e9f;
            } else if (EPI == 2) {
#pragma unroll
                for (int j = 0; j < 8; ++j)
                    v[j] = (v[j] > 0.0f) ? v[j] : expm1f(v[j]);
            }

            *(float4*)(C + base)     = make_float4(v[0], v[1], v[2], v[3]);
            *(float4*)(C + base + 4) = make_float4(v[4], v[5], v[6], v[7]);
        }
    }
}

// In-place masked softmax over rows of 4096. Masked entries arrive as exactly
// -1e9 and must leave as exactly 0 (ref multiplies softmax by the mask).
__global__ __launch_bounds__(256)
void softmax4096(float* __restrict__ S)
{
    const int row = blockIdx.x;
    float* r = S + (size_t)row * MEDGE;
    const int t = threadIdx.x;

    float4 v[4];
#pragma unroll
    for (int i = 0; i < 4; ++i)
        v[i] = ((const float4*)r)[t + (i << 8)];

    float mx = -3.4e38f;
#pragma unroll
    for (int i = 0; i < 4; ++i) {
        mx = fmaxf(mx, fmaxf(fmaxf(v[i].x, v[i].y), fmaxf(v[i].z, v[i].w)));
    }

    __shared__ float red[8];
#pragma unroll
    for (int o = 16; o; o >>= 1) mx = fmaxf(mx, __shfl_xor_sync(0xffffffffu, mx, o));
    if ((t & 31) == 0) red[t >> 5] = mx;
    __syncthreads();
    mx = red[0];
#pragma unroll
    for (int i = 1; i < 8; ++i) mx = fmaxf(mx, red[i]);
    __syncthreads();   // before red reuse

    float s = 0.0f;
#pragma unroll
    for (int i = 0; i < 4; ++i) {
        v[i].x = (v[i].x > -1e8f) ? expf(v[i].x - mx) : 0.0f;
        v[i].y = (v[i].y > -1e8f) ? expf(v[i].y - mx) : 0.0f;
        v[i].z = (v[i].z > -1e8f) ? expf(v[i].z - mx) : 0.0f;
        v[i].w = (v[i].w > -1e8f) ? expf(v[i].w - mx) : 0.0f;
        s += v[i].x + v[i].y + v[i].z + v[i].w;
    }
#pragma unroll
    for (int o = 16; o; o >>= 1) s += __shfl_xor_sync(0xffffffffu, s, o);
    if ((t & 31) == 0) red[t >> 5] = s;
    __syncthreads();
    s = red[0];
#pragma unroll
    for (int i = 1; i < 8; ++i) s += red[i];

    const float inv = 1.0f / s;
#pragma unroll
    for (int i = 0; i < 4; ++i) {
        v[i].x *= inv; v[i].y *= inv; v[i].z *= inv; v[i].w *= inv;
        ((float4*)r)[t + (i << 8)] = v[i];
    }
}

extern "C" void kernel_launch(void* const* d_in, const int* in_sizes, int n_in,
                              void* d_out, int out_size)
{
    (void)in_sizes; (void)n_in; (void)out_size;
    const float* x   = (const float*)d_in[0];
    const float* er  = (const float*)d_in[1];
    const int*   H   = (const int*)d_in[2];
    const float* We  = (const float*)d_in[3];
    const float* Wn  = (const float*)d_in[4];

    float* out  = (float*)d_out;                               // [N, DIM]
    float* Bout = (float*)d_out + (size_t)NNODE * DIMSZ;       // [N, M]

    float *hn_p = nullptr, *he_p = nullptr;
    cudaGetSymbolAddress((void**)&hn_p, g_hn);
    cudaGetSymbolAddress((void**)&he_p, g_he);

    const dim3 blk(256);
    const float scale = 1.0f / 32.0f;   // 1/sqrt(1024)

    // he = e_repr @ W_e^T   [M, DIM]
    gemm128<true, 0><<<dim3(DIMSZ / 128, MEDGE / 128), blk>>>(er, We, he_p, DIMSZ, DIMSZ, nullptr, 0.f);
    // hn = x @ W_n^T        [N, DIM]
    gemm128<true, 0><<<dim3(DIMSZ / 128, NNODE / 128), blk>>>(x, Wn, hn_p, DIMSZ, DIMSZ, nullptr, 0.f);
    // S = (hn @ he^T) * scale, masked -> B output region
    gemm128<true, 1><<<dim3(MEDGE / 128, NNODE / 128), blk>>>(hn_p, he_p, Bout, MEDGE, DIMSZ, H, scale);
    // row softmax (in place; masked -> exact 0)
    softmax4096<<<NNODE, 256>>>(Bout);
    // out = elu(B @ he)     [N, DIM]
    gemm128<false, 2><<<dim3(DIMSZ / 128, NNODE / 128), blk>>>(Bout, he_p, out, DIMSZ, MEDGE, nullptr, 0.f);
}